// round 2
// baseline (speedup 1.0000x reference)
#include <cuda_runtime.h>
#include <cuda_fp16.h>
#include <math.h>

#define MAXN 100000
#define MAXE 1000000
#define HF   64
#define NPW  16          // nodes per warp in fused agg+pool

// ---------------- scratch (device globals) ------------------------------------
__device__ __align__(16) float  g_degw[MAXN];
__device__ __align__(16) float  g_dis[MAXN];
__device__ __align__(16) int    g_cnt[MAXN];
__device__ __align__(16) int    g_cnt2[MAXN];
__device__ __align__(16) int    g_offs[MAXN + 1];
__device__ __align__(16) float2 g_edge[MAXE];               // .x = src (int bits), .y = norm
__device__ __align__(16) __half g_tmp16[(size_t)MAXN * HF]; // GEMM output (gathered)
__device__ __align__(16) float  g_ha [(size_t)MAXN * HF];
__device__ __align__(16) float  g_hb [(size_t)MAXN * HF];
__device__ __align__(16) float  g_den[MAXN];
__device__ __align__(16) float  g_num[MAXN];
__device__ __align__(16) float  g_nw[MAXN];
__device__ __align__(16) float  g_s[256 * HF];
__device__ __align__(16) float  g_wsum[256];

// ---------------- init (nodes + graphs in one launch) --------------------------
__global__ void k_init(int n, int bn) {
    int i = blockIdx.x * blockDim.x + threadIdx.x;
    if (i < n) {
        g_degw[i] = 1.0f;      // self-loop weight
        g_cnt[i]  = 0;
        g_cnt2[i] = 0;
        g_den[i]  = 0.0f;
        g_num[i]  = 0.0f;
    }
    if (i < bn * HF) g_s[i] = 0.0f;
    if (i < bn)      g_wsum[i] = 0.0f;
}

// ---------------- single edge pass: degree + count + softmax accum -------------
// softmax is shift-invariant: use constant shift (w-1)/t instead of per-node max.
// w in [0,1) -> exp arg in [-20,0), no under/overflow; num/den ratio unchanged.
__global__ void k_edge_setup(const int* __restrict__ row, const int* __restrict__ col,
                             const float* __restrict__ ew, int e) {
    int i = blockIdx.x * blockDim.x + threadIdx.x;
    if (i >= e) return;
    int r = row[i], c = col[i];
    float w = ew[i];
    atomicAdd(&g_degw[c], w);
    atomicAdd(&g_cnt[c], 1);
    float a = __expf((w - 1.0f) * 20.0f);
    float wa = w * a;
    atomicAdd(&g_den[r], a);
    atomicAdd(&g_num[r], wa);
    atomicAdd(&g_den[c], a);
    atomicAdd(&g_num[c], wa);
}

__global__ void k_node_finish(int n) {
    int i = blockIdx.x * blockDim.x + threadIdx.x;
    if (i >= n) return;
    g_dis[i] = rsqrtf(g_degw[i]);          // deg >= 1 (self-loop)
    float d = g_den[i];
    g_nw[i] = (d > 0.0f) ? g_num[i] / fmaxf(d, 1e-16f) : 0.0f;
}

// ---------------- single-kernel exclusive scan of g_cnt -> g_offs --------------
__global__ void k_scan_all(int n, int e) {
    __shared__ int tot[1024];
    int chunk = (n + 1023) >> 10;
    int start = threadIdx.x * chunk;
    int end = min(start + chunk, n);
    int s = 0;
    for (int i = start; i < end; i++) s += g_cnt[i];
    tot[threadIdx.x] = s;
    __syncthreads();
    for (int off = 1; off < 1024; off <<= 1) {
        int t = (threadIdx.x >= off) ? tot[threadIdx.x - off] : 0;
        __syncthreads();
        tot[threadIdx.x] += t;
        __syncthreads();
    }
    int run = tot[threadIdx.x] - s;        // exclusive prefix of this chunk
    for (int i = start; i < end; i++) {
        g_offs[i] = run;
        run += g_cnt[i];
    }
    if (threadIdx.x == 0) g_offs[n] = e;
}

// scatter edges into destination-sorted order; pack (src, norm) into 8B
__global__ void k_edge_scatter(const int* __restrict__ row, const int* __restrict__ col,
                               const float* __restrict__ ew, int e) {
    int i = blockIdx.x * blockDim.x + threadIdx.x;
    if (i >= e) return;
    int r = row[i], c = col[i];
    int p = g_offs[c] + atomicAdd(&g_cnt2[c], 1);
    float2 pk;
    pk.x = __int_as_float(r);
    pk.y = g_dis[r] * ew[i] * g_dis[c];
    g_edge[p] = pk;
}

// ---------------- GEMM: [n,64] @ [64,64] -> fp16, optional LeakyReLU on A ------
template <bool LEAKY>
__global__ void k_gemm64(const float* __restrict__ A, const float* __restrict__ W,
                         __half* __restrict__ C, int n) {
    __shared__ float As[64][65];
    __shared__ float Ws[64][64];
    int brow = blockIdx.x * 64;
    for (int i = threadIdx.x; i < 4096; i += 256) {
        int rr = i >> 6, cc = i & 63;
        Ws[rr][cc] = W[i];
        int gr = brow + rr;
        float v = (gr < n) ? A[(size_t)gr * HF + cc] : 0.0f;
        if (LEAKY) v = (v > 0.0f) ? v : 0.01f * v;
        As[rr][cc] = v;
    }
    __syncthreads();
    int r0 = (threadIdx.x >> 4) * 4;
    int c0 = (threadIdx.x & 15) * 4;
    float acc[4][4] = {};
#pragma unroll
    for (int k = 0; k < 64; k++) {
        float a0 = As[r0 + 0][k], a1 = As[r0 + 1][k], a2 = As[r0 + 2][k], a3 = As[r0 + 3][k];
        float4 w4 = *(const float4*)&Ws[k][c0];
        acc[0][0] += a0 * w4.x; acc[0][1] += a0 * w4.y; acc[0][2] += a0 * w4.z; acc[0][3] += a0 * w4.w;
        acc[1][0] += a1 * w4.x; acc[1][1] += a1 * w4.y; acc[1][2] += a1 * w4.z; acc[1][3] += a1 * w4.w;
        acc[2][0] += a2 * w4.x; acc[2][1] += a2 * w4.y; acc[2][2] += a2 * w4.z; acc[2][3] += a2 * w4.w;
        acc[3][0] += a3 * w4.x; acc[3][1] += a3 * w4.y; acc[3][2] += a3 * w4.z; acc[3][3] += a3 * w4.w;
    }
#pragma unroll
    for (int i = 0; i < 4; i++) {
        int gr = brow + r0 + i;
        if (gr < n) {
            __half2* dst = (__half2*)&C[(size_t)gr * HF + c0];
            dst[0] = __floats2half2_rn(acc[i][0], acc[i][1]);
            dst[1] = __floats2half2_rn(acc[i][2], acc[i][3]);
        }
    }
}

// ---------------- segmented aggregation, warp per node (layers 1-2) ------------
__global__ void k_aggregate(const __half2* __restrict__ tmp, const float* __restrict__ bias,
                            float* __restrict__ out, int n) {
    int gt = blockIdx.x * blockDim.x + threadIdx.x;
    int node = gt >> 5;
    int lane = gt & 31;
    if (node >= n) return;
    float d = g_dis[node];
    float sc = d * d;
    float2 self = __half22float2(tmp[(size_t)node * 32 + lane]);
    float ax = sc * self.x;
    float ay = sc * self.y;
    int p = g_offs[node], end = g_offs[node + 1];
    for (; p < end; ++p) {
        float2 pk = g_edge[p];
        int s = __float_as_int(pk.x);
        float2 v = __half22float2(tmp[(size_t)s * 32 + lane]);
        ax += pk.y * v.x;
        ay += pk.y * v.y;
    }
    float2 bb = ((const float2*)bias)[lane];
    float2 o; o.x = ax + bb.x; o.y = ay + bb.y;
    ((float2*)(out + (size_t)node * HF))[lane] = o;
}

// ---------------- fused layer-3 aggregation + weighted pooling -----------------
// batch is sorted -> register-carry accumulation, flush atomics only on graph
// change or warp-chunk end. No h3 materialization at all.
__global__ void k_agg_pool(const __half2* __restrict__ tmp, const float* __restrict__ bias,
                           const int* __restrict__ batch, int n) {
    int warp = (blockIdx.x * blockDim.x + threadIdx.x) >> 5;
    int lane = threadIdx.x & 31;
    int n0 = warp * NPW;
    if (n0 >= n) return;
    int n1 = min(n0 + NPW, n);
    float2 bb = ((const float2*)bias)[lane];
    float px = 0.0f, py = 0.0f, wacc = 0.0f;
    int cb = batch[n0];
    for (int node = n0; node < n1; node++) {
        int b = batch[node];
        if (b != cb) {
            atomicAdd(&g_s[cb * HF + 2 * lane],     px);
            atomicAdd(&g_s[cb * HF + 2 * lane + 1], py);
            if (lane == 0) atomicAdd(&g_wsum[cb], wacc);
            px = py = wacc = 0.0f;
            cb = b;
        }
        float d = g_dis[node];
        float sc = d * d;
        float2 self = __half22float2(tmp[(size_t)node * 32 + lane]);
        float ax = sc * self.x;
        float ay = sc * self.y;
        int p = g_offs[node], end = g_offs[node + 1];
        for (; p < end; ++p) {
            float2 pk = g_edge[p];
            int s = __float_as_int(pk.x);
            float2 v = __half22float2(tmp[(size_t)s * 32 + lane]);
            ax += pk.y * v.x;
            ay += pk.y * v.y;
        }
        float nwv = g_nw[node];
        px += nwv * (ax + bb.x);
        py += nwv * (ay + bb.y);
        wacc += nwv;
    }
    atomicAdd(&g_s[cb * HF + 2 * lane],     px);
    atomicAdd(&g_s[cb * HF + 2 * lane + 1], py);
    if (lane == 0) atomicAdd(&g_wsum[cb], wacc);
}

// ---------------- MLP head: one thread per graph -------------------------------
__global__ void k_head(const float* __restrict__ Wlin, const float* __restrict__ blin,
                       const float* __restrict__ Wout, const float* __restrict__ bout,
                       float* __restrict__ out, int bn) {
    int b = blockIdx.x * blockDim.x + threadIdx.x;
    if (b >= bn) return;
    const int O_PROBS = bn * 10;
    const int O_FEATS = bn * 20;
    const int O_EMB   = O_FEATS + bn * 128;
    const int O_HOUT  = O_EMB + bn * 64;

    float feats[128];
    float ws = fmaxf(g_wsum[b], 1e-16f);
#pragma unroll
    for (int k = 0; k < HF; k++) {
        float sv = g_s[b * HF + k];
        feats[k] = sv;
        feats[HF + k] = sv / ws;
    }
    float emb[64], ho[64];
    for (int j = 0; j < 64; j++) {
        float a = blin[j];
        for (int i = 0; i < 128; i++) a += feats[i] * __ldg(&Wlin[i * 64 + j]);
        emb[j] = a;
        ho[j] = fmaxf(a, 0.0f);
    }
    float lg[10];
    for (int c = 0; c < 10; c++) {
        float a = bout[c];
        for (int j = 0; j < 64; j++) a += ho[j] * __ldg(&Wout[j * 10 + c]);
        lg[c] = a;
    }
    float mx = lg[0];
#pragma unroll
    for (int c = 1; c < 10; c++) mx = fmaxf(mx, lg[c]);
    float ex[10], den = 0.0f;
#pragma unroll
    for (int c = 0; c < 10; c++) { ex[c] = expf(lg[c] - mx); den += ex[c]; }
    float inv = 1.0f / den;

    for (int c = 0; c < 10; c++) {
        out[b * 10 + c] = lg[c];
        out[O_PROBS + b * 10 + c] = ex[c] * inv;
    }
    for (int i = 0; i < 128; i++) out[O_FEATS + b * 128 + i] = feats[i];
    for (int j = 0; j < 64; j++) {
        out[O_EMB  + b * 64 + j] = emb[j];
        out[O_HOUT + b * 64 + j] = ho[j];
    }
}

// -------------------------------------------------------------------------------
extern "C" void kernel_launch(void* const* d_in, const int* in_sizes, int n_in,
                              void* d_out, int out_size) {
    const float* x    = (const float*)d_in[0];
    const int*   ei   = (const int*)  d_in[1];
    const float* ew   = (const float*)d_in[2];
    const int*   batch= (const int*)  d_in[3];
    const float* W1 = (const float*)d_in[4];  const float* b1 = (const float*)d_in[5];
    const float* W2 = (const float*)d_in[6];  const float* b2 = (const float*)d_in[7];
    const float* W3 = (const float*)d_in[8];  const float* b3 = (const float*)d_in[9];
    const float* Wlin = (const float*)d_in[10]; const float* blin = (const float*)d_in[11];
    const float* Wout = (const float*)d_in[12]; const float* bout = (const float*)d_in[13];
    float* out = (float*)d_out;

    int n  = in_sizes[0] / HF;
    int e  = in_sizes[2];
    int bn = out_size / 276;

    const int* row = ei;
    const int* col = ei + e;

    __half *p_tmp16;
    float *p_ha, *p_hb;
    cudaGetSymbolAddress((void**)&p_tmp16, g_tmp16);
    cudaGetSymbolAddress((void**)&p_ha,  g_ha);
    cudaGetSymbolAddress((void**)&p_hb,  g_hb);

    const int T = 256;
    int initMax = max(n, bn * HF);
    int nBlkE = (e + T - 1) / T;
    int nBlkN = (n + T - 1) / T;
    int nBlkW = ((n * 32) + T - 1) / T;              // warp-per-node
    int nBlkP = ((((n + NPW - 1) / NPW) * 32) + T - 1) / T;

    // setup
    k_init<<<(initMax + T - 1) / T, T>>>(n, bn);
    k_edge_setup<<<nBlkE, T>>>(row, col, ew, e);
    k_node_finish<<<nBlkN, T>>>(n);
    k_scan_all<<<1, 1024>>>(n, e);
    k_edge_scatter<<<nBlkE, T>>>(row, col, ew, e);

    int gemmBlks = (n + 63) / 64;
    // layer 1
    k_gemm64<false><<<gemmBlks, 256>>>(x, W1, p_tmp16, n);
    k_aggregate<<<nBlkW, T>>>((const __half2*)p_tmp16, b1, p_ha, n);
    // layer 2
    k_gemm64<true><<<gemmBlks, 256>>>(p_ha, W2, p_tmp16, n);
    k_aggregate<<<nBlkW, T>>>((const __half2*)p_tmp16, b2, p_hb, n);
    // layer 3 fused with pooling (h3 never materialized)
    k_gemm64<true><<<gemmBlks, 256>>>(p_hb, W3, p_tmp16, n);
    k_agg_pool<<<nBlkP, T>>>((const __half2*)p_tmp16, b3, batch, n);

    // head
    k_head<<<(bn + 127) / 128, 128>>>(Wlin, blin, Wout, bout, out, bn);
}

// round 3
// speedup vs baseline: 1.2302x; 1.2302x over previous
#include <cuda_runtime.h>
#include <cuda_fp16.h>
#include <math.h>

#define MAXN 100000
#define MAXE 1000000
#define HF   64
#define NPW  16          // nodes per warp in fused agg+pool
#define SBLK 1024        // scan block size

// ---------------- scratch (device globals) ------------------------------------
__device__ __align__(16) float  g_degw[MAXN];
__device__ __align__(16) float  g_dis[MAXN];
__device__ __align__(16) int    g_cnt[MAXN];
__device__ __align__(16) int    g_cnt2[MAXN];
__device__ __align__(16) int    g_bscan[MAXN];
__device__ __align__(16) int    g_bsum[256];
__device__ __align__(16) int    g_offs[MAXN + 1];
__device__ __align__(16) float2 g_edge[MAXE];               // .x = src (int bits), .y = norm
__device__ __align__(16) __half g_tmp16[(size_t)MAXN * HF]; // GEMM output (gathered)
__device__ __align__(16) float  g_ha [(size_t)MAXN * HF];
__device__ __align__(16) float  g_hb [(size_t)MAXN * HF];
__device__ __align__(16) float  g_den[MAXN];
__device__ __align__(16) float  g_num[MAXN];
__device__ __align__(16) float  g_nw[MAXN];
__device__ __align__(16) float  g_s[256 * HF];
__device__ __align__(16) float  g_wsum[256];

// ---------------- init (nodes + graphs in one launch) --------------------------
__global__ void k_init(int n, int bn) {
    int i = blockIdx.x * blockDim.x + threadIdx.x;
    if (i < n) {
        g_degw[i] = 1.0f;      // self-loop weight
        g_cnt[i]  = 0;
        g_cnt2[i] = 0;
        g_den[i]  = 0.0f;
        g_num[i]  = 0.0f;
    }
    if (i < bn * HF) g_s[i] = 0.0f;
    if (i < bn)      g_wsum[i] = 0.0f;
}

// ---------------- single edge pass: degree + count + softmax accum -------------
// softmax is shift-invariant: constant shift (w-1)/t replaces per-node max.
// w in [0,1) -> exp arg in [-20,0): no under/overflow; num/den ratio unchanged.
__global__ void k_edge_setup(const int* __restrict__ row, const int* __restrict__ col,
                             const float* __restrict__ ew, int e) {
    int i = blockIdx.x * blockDim.x + threadIdx.x;
    if (i >= e) return;
    int r = row[i], c = col[i];
    float w = ew[i];
    atomicAdd(&g_degw[c], w);
    atomicAdd(&g_cnt[c], 1);
    float a = __expf((w - 1.0f) * 20.0f);
    float wa = w * a;
    atomicAdd(&g_den[r], a);
    atomicAdd(&g_num[r], wa);
    atomicAdd(&g_den[c], a);
    atomicAdd(&g_num[c], wa);
}

// ---- scan phase 1: per-block inclusive scan of g_cnt; fused node finish -------
__global__ void k_scan1(int n) {
    __shared__ int sh[SBLK];
    int i = blockIdx.x * SBLK + threadIdx.x;
    int v = (i < n) ? g_cnt[i] : 0;
    sh[threadIdx.x] = v;
    __syncthreads();
    for (int off = 1; off < SBLK; off <<= 1) {
        int t = (threadIdx.x >= off) ? sh[threadIdx.x - off] : 0;
        __syncthreads();
        sh[threadIdx.x] += t;
        __syncthreads();
    }
    if (i < n) g_bscan[i] = sh[threadIdx.x];
    if (threadIdx.x == SBLK - 1) g_bsum[blockIdx.x] = sh[threadIdx.x];

    // fused elementwise node postprocessing (independent of the scan)
    if (i < n) {
        g_dis[i] = rsqrtf(g_degw[i]);      // deg >= 1 (self-loop)
        float d = g_den[i];
        g_nw[i] = (d > 0.0f) ? g_num[i] / fmaxf(d, 1e-16f) : 0.0f;
    }
}

// ---- scan phase 2: exclusive scan of ~98 block sums (tiny, 1 thread) ----------
__global__ void k_scan2(int nb) {
    if (threadIdx.x == 0) {
        int run = 0;
        for (int b = 0; b < nb; b++) { int t = g_bsum[b]; g_bsum[b] = run; run += t; }
    }
}

// ---- scan phase 3: combine into exclusive offsets ------------------------------
__global__ void k_scan3(int n, int e) {
    int i = blockIdx.x * blockDim.x + threadIdx.x;
    if (i < n) g_offs[i] = g_bsum[i / SBLK] + g_bscan[i] - g_cnt[i];
    if (i == 0) g_offs[n] = e;
}

// scatter edges into destination-sorted order; pack (src, norm) into 8B
__global__ void k_edge_scatter(const int* __restrict__ row, const int* __restrict__ col,
                               const float* __restrict__ ew, int e) {
    int i = blockIdx.x * blockDim.x + threadIdx.x;
    if (i >= e) return;
    int r = row[i], c = col[i];
    int p = g_offs[c] + atomicAdd(&g_cnt2[c], 1);
    float2 pk;
    pk.x = __int_as_float(r);
    pk.y = g_dis[r] * ew[i] * g_dis[c];
    g_edge[p] = pk;
}

// ---------------- GEMM: [n,64] @ [64,64] -> fp16, optional LeakyReLU on A ------
template <bool LEAKY>
__global__ void k_gemm64(const float* __restrict__ A, const float* __restrict__ W,
                         __half* __restrict__ C, int n) {
    __shared__ float As[64][65];
    __shared__ float Ws[64][64];
    int brow = blockIdx.x * 64;
    for (int i = threadIdx.x; i < 4096; i += 256) {
        int rr = i >> 6, cc = i & 63;
        Ws[rr][cc] = W[i];
        int gr = brow + rr;
        float v = (gr < n) ? A[(size_t)gr * HF + cc] : 0.0f;
        if (LEAKY) v = (v > 0.0f) ? v : 0.01f * v;
        As[rr][cc] = v;
    }
    __syncthreads();
    int r0 = (threadIdx.x >> 4) * 4;
    int c0 = (threadIdx.x & 15) * 4;
    float acc[4][4] = {};
#pragma unroll
    for (int k = 0; k < 64; k++) {
        float a0 = As[r0 + 0][k], a1 = As[r0 + 1][k], a2 = As[r0 + 2][k], a3 = As[r0 + 3][k];
        float4 w4 = *(const float4*)&Ws[k][c0];
        acc[0][0] += a0 * w4.x; acc[0][1] += a0 * w4.y; acc[0][2] += a0 * w4.z; acc[0][3] += a0 * w4.w;
        acc[1][0] += a1 * w4.x; acc[1][1] += a1 * w4.y; acc[1][2] += a1 * w4.z; acc[1][3] += a1 * w4.w;
        acc[2][0] += a2 * w4.x; acc[2][1] += a2 * w4.y; acc[2][2] += a2 * w4.z; acc[2][3] += a2 * w4.w;
        acc[3][0] += a3 * w4.x; acc[3][1] += a3 * w4.y; acc[3][2] += a3 * w4.z; acc[3][3] += a3 * w4.w;
    }
#pragma unroll
    for (int i = 0; i < 4; i++) {
        int gr = brow + r0 + i;
        if (gr < n) {
            __half2* dst = (__half2*)&C[(size_t)gr * HF + c0];
            dst[0] = __floats2half2_rn(acc[i][0], acc[i][1]);
            dst[1] = __floats2half2_rn(acc[i][2], acc[i][3]);
        }
    }
}

// ---------------- segmented aggregation, warp per node (layers 1-2) ------------
__global__ void k_aggregate(const __half2* __restrict__ tmp, const float* __restrict__ bias,
                            float* __restrict__ out, int n) {
    int gt = blockIdx.x * blockDim.x + threadIdx.x;
    int node = gt >> 5;
    int lane = gt & 31;
    if (node >= n) return;
    float d = g_dis[node];
    float sc = d * d;
    float2 self = __half22float2(tmp[(size_t)node * 32 + lane]);
    float ax = sc * self.x;
    float ay = sc * self.y;
    int p = g_offs[node], end = g_offs[node + 1];
    for (; p < end; ++p) {
        float2 pk = g_edge[p];
        int s = __float_as_int(pk.x);
        float2 v = __half22float2(tmp[(size_t)s * 32 + lane]);
        ax += pk.y * v.x;
        ay += pk.y * v.y;
    }
    float2 bb = ((const float2*)bias)[lane];
    float2 o; o.x = ax + bb.x; o.y = ay + bb.y;
    ((float2*)(out + (size_t)node * HF))[lane] = o;
}

// ---------------- fused layer-3 aggregation + weighted pooling -----------------
__global__ void k_agg_pool(const __half2* __restrict__ tmp, const float* __restrict__ bias,
                           const int* __restrict__ batch, int n) {
    int warp = (blockIdx.x * blockDim.x + threadIdx.x) >> 5;
    int lane = threadIdx.x & 31;
    int n0 = warp * NPW;
    if (n0 >= n) return;
    int n1 = min(n0 + NPW, n);
    float2 bb = ((const float2*)bias)[lane];
    float px = 0.0f, py = 0.0f, wacc = 0.0f;
    int cb = batch[n0];
    for (int node = n0; node < n1; node++) {
        int b = batch[node];
        if (b != cb) {
            atomicAdd(&g_s[cb * HF + 2 * lane],     px);
            atomicAdd(&g_s[cb * HF + 2 * lane + 1], py);
            if (lane == 0) atomicAdd(&g_wsum[cb], wacc);
            px = py = wacc = 0.0f;
            cb = b;
        }
        float d = g_dis[node];
        float sc = d * d;
        float2 self = __half22float2(tmp[(size_t)node * 32 + lane]);
        float ax = sc * self.x;
        float ay = sc * self.y;
        int p = g_offs[node], end = g_offs[node + 1];
        for (; p < end; ++p) {
            float2 pk = g_edge[p];
            int s = __float_as_int(pk.x);
            float2 v = __half22float2(tmp[(size_t)s * 32 + lane]);
            ax += pk.y * v.x;
            ay += pk.y * v.y;
        }
        float nwv = g_nw[node];
        px += nwv * (ax + bb.x);
        py += nwv * (ay + bb.y);
        wacc += nwv;
    }
    atomicAdd(&g_s[cb * HF + 2 * lane],     px);
    atomicAdd(&g_s[cb * HF + 2 * lane + 1], py);
    if (lane == 0) atomicAdd(&g_wsum[cb], wacc);
}

// ---------------- MLP head: one thread per graph -------------------------------
__global__ void k_head(const float* __restrict__ Wlin, const float* __restrict__ blin,
                       const float* __restrict__ Wout, const float* __restrict__ bout,
                       float* __restrict__ out, int bn) {
    int b = blockIdx.x * blockDim.x + threadIdx.x;
    if (b >= bn) return;
    const int O_PROBS = bn * 10;
    const int O_FEATS = bn * 20;
    const int O_EMB   = O_FEATS + bn * 128;
    const int O_HOUT  = O_EMB + bn * 64;

    float feats[128];
    float ws = fmaxf(g_wsum[b], 1e-16f);
#pragma unroll
    for (int k = 0; k < HF; k++) {
        float sv = g_s[b * HF + k];
        feats[k] = sv;
        feats[HF + k] = sv / ws;
    }
    float emb[64], ho[64];
    for (int j = 0; j < 64; j++) {
        float a = blin[j];
        for (int i = 0; i < 128; i++) a += feats[i] * __ldg(&Wlin[i * 64 + j]);
        emb[j] = a;
        ho[j] = fmaxf(a, 0.0f);
    }
    float lg[10];
    for (int c = 0; c < 10; c++) {
        float a = bout[c];
        for (int j = 0; j < 64; j++) a += ho[j] * __ldg(&Wout[j * 10 + c]);
        lg[c] = a;
    }
    float mx = lg[0];
#pragma unroll
    for (int c = 1; c < 10; c++) mx = fmaxf(mx, lg[c]);
    float ex[10], den = 0.0f;
#pragma unroll
    for (int c = 0; c < 10; c++) { ex[c] = expf(lg[c] - mx); den += ex[c]; }
    float inv = 1.0f / den;

    for (int c = 0; c < 10; c++) {
        out[b * 10 + c] = lg[c];
        out[O_PROBS + b * 10 + c] = ex[c] * inv;
    }
    for (int i = 0; i < 128; i++) out[O_FEATS + b * 128 + i] = feats[i];
    for (int j = 0; j < 64; j++) {
        out[O_EMB  + b * 64 + j] = emb[j];
        out[O_HOUT + b * 64 + j] = ho[j];
    }
}

// -------------------------------------------------------------------------------
extern "C" void kernel_launch(void* const* d_in, const int* in_sizes, int n_in,
                              void* d_out, int out_size) {
    const float* x    = (const float*)d_in[0];
    const int*   ei   = (const int*)  d_in[1];
    const float* ew   = (const float*)d_in[2];
    const int*   batch= (const int*)  d_in[3];
    const float* W1 = (const float*)d_in[4];  const float* b1 = (const float*)d_in[5];
    const float* W2 = (const float*)d_in[6];  const float* b2 = (const float*)d_in[7];
    const float* W3 = (const float*)d_in[8];  const float* b3 = (const float*)d_in[9];
    const float* Wlin = (const float*)d_in[10]; const float* blin = (const float*)d_in[11];
    const float* Wout = (const float*)d_in[12]; const float* bout = (const float*)d_in[13];
    float* out = (float*)d_out;

    int n  = in_sizes[0] / HF;
    int e  = in_sizes[2];
    int bn = out_size / 276;

    const int* row = ei;
    const int* col = ei + e;

    __half *p_tmp16;
    float *p_ha, *p_hb;
    cudaGetSymbolAddress((void**)&p_tmp16, g_tmp16);
    cudaGetSymbolAddress((void**)&p_ha,  g_ha);
    cudaGetSymbolAddress((void**)&p_hb,  g_hb);

    const int T = 256;
    int initMax = max(n, bn * HF);
    int nBlkE = (e + T - 1) / T;
    int nBlkW = ((n * 32) + T - 1) / T;              // warp-per-node
    int nBlkP = ((((n + NPW - 1) / NPW) * 32) + T - 1) / T;
    int nb = (n + SBLK - 1) / SBLK;

    // setup
    k_init<<<(initMax + T - 1) / T, T>>>(n, bn);
    k_edge_setup<<<nBlkE, T>>>(row, col, ew, e);
    k_scan1<<<nb, SBLK>>>(n);                        // + fused node finish
    k_scan2<<<1, 32>>>(nb);
    k_scan3<<<(n + 1 + T - 1) / T, T>>>(n, e);
    k_edge_scatter<<<nBlkE, T>>>(row, col, ew, e);

    int gemmBlks = (n + 63) / 64;
    // layer 1
    k_gemm64<false><<<gemmBlks, 256>>>(x, W1, p_tmp16, n);
    k_aggregate<<<nBlkW, T>>>((const __half2*)p_tmp16, b1, p_ha, n);
    // layer 2
    k_gemm64<true><<<gemmBlks, 256>>>(p_ha, W2, p_tmp16, n);
    k_aggregate<<<nBlkW, T>>>((const __half2*)p_tmp16, b2, p_hb, n);
    // layer 3 fused with pooling (h3 never materialized)
    k_gemm64<true><<<gemmBlks, 256>>>(p_hb, W3, p_tmp16, n);
    k_agg_pool<<<nBlkP, T>>>((const __half2*)p_tmp16, b3, batch, n);

    // head
    k_head<<<(bn + 127) / 128, 128>>>(Wlin, blin, Wout, bout, out, bn);
}

// round 4
// speedup vs baseline: 1.4314x; 1.1635x over previous
#include <cuda_runtime.h>
#include <cuda_fp16.h>
#include <math.h>

#define MAXN 100000
#define MAXE 1000000
#define HF   64
#define NPW  16          // nodes per warp in agg_pool
#define SBLK 1024        // scan block size

// ---------------- scratch (device globals) ------------------------------------
__device__ __align__(16) float2 g_degcnt[MAXN];   // .x = weighted degree (incl self), .y = edge count (float)
__device__ __align__(16) float2 g_dennum[MAXN];   // softmax den/num accumulators
__device__ __align__(16) float  g_dis[MAXN];
__device__ __align__(16) float  g_nw[MAXN];
__device__ __align__(16) int    g_cnt2[MAXN];
__device__ __align__(16) int    g_bscan[MAXN];    // exclusive-in-block scan of cnt
__device__ __align__(16) int    g_bsum[128];
__device__ __align__(16) int    g_offs[MAXN + 1];
__device__ __align__(16) float2 g_edge[MAXE];     // .x = src (int bits), .y = norm
__device__ __align__(16) __half g_tA[(size_t)MAXN * HF];
__device__ __align__(16) __half g_tB[(size_t)MAXN * HF];
__device__ __align__(16) float  g_s[256 * HF];
__device__ __align__(16) float  g_wsum[256];

// ---------------- init ----------------------------------------------------------
__global__ void k_init(int n, int bn) {
    int i = blockIdx.x * blockDim.x + threadIdx.x;
    if (i < n) {
        g_degcnt[i] = make_float2(1.0f, 0.0f);   // self-loop weight, 0 edges
        g_dennum[i] = make_float2(0.0f, 0.0f);
        g_cnt2[i]   = 0;
    }
    if (i < bn * HF) g_s[i] = 0.0f;
    if (i < bn)      g_wsum[i] = 0.0f;
}

// ---------------- single edge pass: 3 vector atomics per edge -------------------
// softmax shift-invariance: constant shift (w-1)/t, w in [0,1) -> no overflow.
__global__ void k_edge_setup(const int* __restrict__ row, const int* __restrict__ col,
                             const float* __restrict__ ew, int e) {
    int i = blockIdx.x * blockDim.x + threadIdx.x;
    if (i >= e) return;
    int r = row[i], c = col[i];
    float w = ew[i];
    atomicAdd(&g_degcnt[c], make_float2(w, 1.0f));
    float a = __expf((w - 1.0f) * 20.0f);
    float2 dn = make_float2(a, w * a);
    atomicAdd(&g_dennum[r], dn);
    atomicAdd(&g_dennum[c], dn);
}

// ---- scan phase 1: per-block exclusive scan of cnt; fused node finish ----------
__global__ void k_scan1(int n) {
    __shared__ int sh[SBLK];
    int i = blockIdx.x * SBLK + threadIdx.x;
    int v = 0;
    if (i < n) {
        float2 dc = g_degcnt[i];
        v = (int)dc.y;
        g_dis[i] = rsqrtf(dc.x);                    // deg >= 1 (self-loop)
        float2 dn = g_dennum[i];
        g_nw[i] = (dn.x > 0.0f) ? dn.y / fmaxf(dn.x, 1e-16f) : 0.0f;
    }
    sh[threadIdx.x] = v;
    __syncthreads();
    for (int off = 1; off < SBLK; off <<= 1) {
        int t = (threadIdx.x >= off) ? sh[threadIdx.x - off] : 0;
        __syncthreads();
        sh[threadIdx.x] += t;
        __syncthreads();
    }
    if (i < n) g_bscan[i] = sh[threadIdx.x] - v;    // exclusive within block
    if (threadIdx.x == SBLK - 1) g_bsum[blockIdx.x] = sh[threadIdx.x];
}

// ---- scan phase 2: parallel exclusive scan of <=128 block sums -----------------
__global__ void k_scan2(int nb) {
    __shared__ int sh[128];
    int t = threadIdx.x;
    int v = (t < nb) ? g_bsum[t] : 0;
    sh[t] = v;
    __syncthreads();
    for (int off = 1; off < 128; off <<= 1) {
        int u = (t >= off) ? sh[t - off] : 0;
        __syncthreads();
        sh[t] += u;
        __syncthreads();
    }
    if (t < nb) g_bsum[t] = sh[t] - v;              // exclusive
}

// ---- scan phase 3: combine ------------------------------------------------------
__global__ void k_scan3(int n, int e) {
    int i = blockIdx.x * blockDim.x + threadIdx.x;
    if (i < n) g_offs[i] = g_bsum[i / SBLK] + g_bscan[i];
    if (i == 0) g_offs[n] = e;
}

// scatter edges into destination-sorted order; pack (src, norm) into 8B
__global__ void k_edge_scatter(const int* __restrict__ row, const int* __restrict__ col,
                               const float* __restrict__ ew, int e) {
    int i = blockIdx.x * blockDim.x + threadIdx.x;
    if (i >= e) return;
    int r = row[i], c = col[i];
    int p = g_offs[c] + atomicAdd(&g_cnt2[c], 1);
    float2 pk;
    pk.x = __int_as_float(r);
    pk.y = g_dis[r] * ew[i] * g_dis[c];
    g_edge[p] = pk;
}

// ---------------- GEMM layer 1: x(fp32)[n,64] @ W1 -> fp16 ----------------------
__global__ void k_gemm64(const float* __restrict__ A, const float* __restrict__ W,
                         __half* __restrict__ C, int n) {
    __shared__ float As[64][65];
    __shared__ float Ws[64][64];
    int brow = blockIdx.x * 64;
    for (int i = threadIdx.x; i < 4096; i += 256) {
        int rr = i >> 6, cc = i & 63;
        Ws[rr][cc] = W[i];
        int gr = brow + rr;
        As[rr][cc] = (gr < n) ? A[(size_t)gr * HF + cc] : 0.0f;
    }
    __syncthreads();
    int r0 = (threadIdx.x >> 4) * 4;
    int c0 = (threadIdx.x & 15) * 4;
    float acc[4][4] = {};
#pragma unroll
    for (int k = 0; k < 64; k++) {
        float a0 = As[r0 + 0][k], a1 = As[r0 + 1][k], a2 = As[r0 + 2][k], a3 = As[r0 + 3][k];
        float4 w4 = *(const float4*)&Ws[k][c0];
        acc[0][0] += a0 * w4.x; acc[0][1] += a0 * w4.y; acc[0][2] += a0 * w4.z; acc[0][3] += a0 * w4.w;
        acc[1][0] += a1 * w4.x; acc[1][1] += a1 * w4.y; acc[1][2] += a1 * w4.z; acc[1][3] += a1 * w4.w;
        acc[2][0] += a2 * w4.x; acc[2][1] += a2 * w4.y; acc[2][2] += a2 * w4.z; acc[2][3] += a2 * w4.w;
        acc[3][0] += a3 * w4.x; acc[3][1] += a3 * w4.y; acc[3][2] += a3 * w4.z; acc[3][3] += a3 * w4.w;
    }
#pragma unroll
    for (int i = 0; i < 4; i++) {
        int gr = brow + r0 + i;
        if (gr < n) {
            __half2* dst = (__half2*)&C[(size_t)gr * HF + c0];
            dst[0] = __floats2half2_rn(acc[i][0], acc[i][1]);
            dst[1] = __floats2half2_rn(acc[i][2], acc[i][3]);
        }
    }
}

// ---------------- fused aggregate(+bias+LeakyReLU) -> GEMM ----------------------
// Block owns nodes [64b, 64b+64). 8 warps aggregate 8 nodes each into shared,
// then the block GEMMs shared @ W -> fp16 output. No fp32 h round-trip.
__global__ void k_agg_gemm(const __half2* __restrict__ tmp, const float* __restrict__ bias,
                           const float* __restrict__ W, __half* __restrict__ C, int n) {
    __shared__ float As[64][65];
    __shared__ float Ws[64][64];
    int brow = blockIdx.x * 64;
    int wid = threadIdx.x >> 5;
    int lane = threadIdx.x & 31;

    for (int i = threadIdx.x; i < 4096; i += 256) {
        Ws[i >> 6][i & 63] = W[i];
    }

    float2 bb = ((const float2*)bias)[lane];
#pragma unroll
    for (int j = 0; j < 8; j++) {
        int rr = wid * 8 + j;
        int node = brow + rr;
        float ax = 0.0f, ay = 0.0f;
        if (node < n) {
            float d = g_dis[node];
            float sc = d * d;
            float2 self = __half22float2(tmp[(size_t)node * 32 + lane]);
            ax = sc * self.x;
            ay = sc * self.y;
            int p = g_offs[node], end = g_offs[node + 1];
            for (; p < end; ++p) {
                float2 pk = g_edge[p];
                int s = __float_as_int(pk.x);
                float2 v = __half22float2(tmp[(size_t)s * 32 + lane]);
                ax += pk.y * v.x;
                ay += pk.y * v.y;
            }
            ax += bb.x; ay += bb.y;
            ax = (ax > 0.0f) ? ax : 0.01f * ax;     // LeakyReLU
            ay = (ay > 0.0f) ? ay : 0.01f * ay;
        }
        As[rr][2 * lane]     = ax;
        As[rr][2 * lane + 1] = ay;
    }
    __syncthreads();

    int r0 = (threadIdx.x >> 4) * 4;
    int c0 = (threadIdx.x & 15) * 4;
    float acc[4][4] = {};
#pragma unroll
    for (int k = 0; k < 64; k++) {
        float a0 = As[r0 + 0][k], a1 = As[r0 + 1][k], a2 = As[r0 + 2][k], a3 = As[r0 + 3][k];
        float4 w4 = *(const float4*)&Ws[k][c0];
        acc[0][0] += a0 * w4.x; acc[0][1] += a0 * w4.y; acc[0][2] += a0 * w4.z; acc[0][3] += a0 * w4.w;
        acc[1][0] += a1 * w4.x; acc[1][1] += a1 * w4.y; acc[1][2] += a1 * w4.z; acc[1][3] += a1 * w4.w;
        acc[2][0] += a2 * w4.x; acc[2][1] += a2 * w4.y; acc[2][2] += a2 * w4.z; acc[2][3] += a2 * w4.w;
        acc[3][0] += a3 * w4.x; acc[3][1] += a3 * w4.y; acc[3][2] += a3 * w4.z; acc[3][3] += a3 * w4.w;
    }
#pragma unroll
    for (int i = 0; i < 4; i++) {
        int gr = brow + r0 + i;
        if (gr < n) {
            __half2* dst = (__half2*)&C[(size_t)gr * HF + c0];
            dst[0] = __floats2half2_rn(acc[i][0], acc[i][1]);
            dst[1] = __floats2half2_rn(acc[i][2], acc[i][3]);
        }
    }
}

// ---------------- fused layer-3 aggregation + weighted pooling ------------------
__global__ void k_agg_pool(const __half2* __restrict__ tmp, const float* __restrict__ bias,
                           const int* __restrict__ batch, int n) {
    int warp = (blockIdx.x * blockDim.x + threadIdx.x) >> 5;
    int lane = threadIdx.x & 31;
    int n0 = warp * NPW;
    if (n0 >= n) return;
    int n1 = min(n0 + NPW, n);
    float2 bb = ((const float2*)bias)[lane];
    float px = 0.0f, py = 0.0f, wacc = 0.0f;
    int cb = batch[n0];
    for (int node = n0; node < n1; node++) {
        int b = batch[node];
        if (b != cb) {
            atomicAdd(&g_s[cb * HF + 2 * lane],     px);
            atomicAdd(&g_s[cb * HF + 2 * lane + 1], py);
            if (lane == 0) atomicAdd(&g_wsum[cb], wacc);
            px = py = wacc = 0.0f;
            cb = b;
        }
        float d = g_dis[node];
        float sc = d * d;
        float2 self = __half22float2(tmp[(size_t)node * 32 + lane]);
        float ax = sc * self.x;
        float ay = sc * self.y;
        int p = g_offs[node], end = g_offs[node + 1];
        for (; p < end; ++p) {
            float2 pk = g_edge[p];
            int s = __float_as_int(pk.x);
            float2 v = __half22float2(tmp[(size_t)s * 32 + lane]);
            ax += pk.y * v.x;
            ay += pk.y * v.y;
        }
        float nwv = g_nw[node];
        px += nwv * (ax + bb.x);
        py += nwv * (ay + bb.y);
        wacc += nwv;
    }
    atomicAdd(&g_s[cb * HF + 2 * lane],     px);
    atomicAdd(&g_s[cb * HF + 2 * lane + 1], py);
    if (lane == 0) atomicAdd(&g_wsum[cb], wacc);
}

// ---------------- MLP head: one thread per graph ---------------------------------
__global__ void k_head(const float* __restrict__ Wlin, const float* __restrict__ blin,
                       const float* __restrict__ Wout, const float* __restrict__ bout,
                       float* __restrict__ out, int bn) {
    int b = blockIdx.x * blockDim.x + threadIdx.x;
    if (b >= bn) return;
    const int O_PROBS = bn * 10;
    const int O_FEATS = bn * 20;
    const int O_EMB   = O_FEATS + bn * 128;
    const int O_HOUT  = O_EMB + bn * 64;

    float feats[128];
    float ws = fmaxf(g_wsum[b], 1e-16f);
#pragma unroll
    for (int k = 0; k < HF; k++) {
        float sv = g_s[b * HF + k];
        feats[k] = sv;
        feats[HF + k] = sv / ws;
    }
    float emb[64], ho[64];
    for (int j = 0; j < 64; j++) {
        float a = blin[j];
        for (int i = 0; i < 128; i++) a += feats[i] * __ldg(&Wlin[i * 64 + j]);
        emb[j] = a;
        ho[j] = fmaxf(a, 0.0f);
    }
    float lg[10];
    for (int c = 0; c < 10; c++) {
        float a = bout[c];
        for (int j = 0; j < 64; j++) a += ho[j] * __ldg(&Wout[j * 10 + c]);
        lg[c] = a;
    }
    float mx = lg[0];
#pragma unroll
    for (int c = 1; c < 10; c++) mx = fmaxf(mx, lg[c]);
    float ex[10], den = 0.0f;
#pragma unroll
    for (int c = 0; c < 10; c++) { ex[c] = expf(lg[c] - mx); den += ex[c]; }
    float inv = 1.0f / den;

    for (int c = 0; c < 10; c++) {
        out[b * 10 + c] = lg[c];
        out[O_PROBS + b * 10 + c] = ex[c] * inv;
    }
    for (int i = 0; i < 128; i++) out[O_FEATS + b * 128 + i] = feats[i];
    for (int j = 0; j < 64; j++) {
        out[O_EMB  + b * 64 + j] = emb[j];
        out[O_HOUT + b * 64 + j] = ho[j];
    }
}

// ---------------------------------------------------------------------------------
extern "C" void kernel_launch(void* const* d_in, const int* in_sizes, int n_in,
                              void* d_out, int out_size) {
    const float* x    = (const float*)d_in[0];
    const int*   ei   = (const int*)  d_in[1];
    const float* ew   = (const float*)d_in[2];
    const int*   batch= (const int*)  d_in[3];
    const float* W1 = (const float*)d_in[4];  const float* b1 = (const float*)d_in[5];
    const float* W2 = (const float*)d_in[6];  const float* b2 = (const float*)d_in[7];
    const float* W3 = (const float*)d_in[8];  const float* b3 = (const float*)d_in[9];
    const float* Wlin = (const float*)d_in[10]; const float* blin = (const float*)d_in[11];
    const float* Wout = (const float*)d_in[12]; const float* bout = (const float*)d_in[13];
    float* out = (float*)d_out;

    int n  = in_sizes[0] / HF;
    int e  = in_sizes[2];
    int bn = out_size / 276;

    const int* row = ei;
    const int* col = ei + e;

    __half *p_tA, *p_tB;
    cudaGetSymbolAddress((void**)&p_tA, g_tA);
    cudaGetSymbolAddress((void**)&p_tB, g_tB);

    const int T = 256;
    int initMax = max(n, bn * HF);
    int nBlkE = (e + T - 1) / T;
    int nBlkP = ((((n + NPW - 1) / NPW) * 32) + T - 1) / T;
    int nb = (n + SBLK - 1) / SBLK;

    // setup
    k_init<<<(initMax + T - 1) / T, T>>>(n, bn);
    k_edge_setup<<<nBlkE, T>>>(row, col, ew, e);
    k_scan1<<<nb, SBLK>>>(n);
    k_scan2<<<1, 128>>>(nb);
    k_scan3<<<(n + 1 + T - 1) / T, T>>>(n, e);
    k_edge_scatter<<<nBlkE, T>>>(row, col, ew, e);

    int gemmBlks = (n + 63) / 64;
    // layer 1 GEMM
    k_gemm64<<<gemmBlks, 256>>>(x, W1, p_tA, n);
    // layer 1 aggregate + LeakyReLU fused with layer 2 GEMM
    k_agg_gemm<<<gemmBlks, 256>>>((const __half2*)p_tA, b1, W2, p_tB, n);
    // layer 2 aggregate + LeakyReLU fused with layer 3 GEMM
    k_agg_gemm<<<gemmBlks, 256>>>((const __half2*)p_tB, b2, W3, p_tA, n);
    // layer 3 aggregate fused with pooling
    k_agg_pool<<<nBlkP, T>>>((const __half2*)p_tA, b3, batch, n);

    // head
    k_head<<<(bn + 127) / 128, 128>>>(Wlin, blin, Wout, bout, out, bn);
}

// round 5
// speedup vs baseline: 1.4813x; 1.0349x over previous
#include <cuda_runtime.h>
#include <cuda_fp16.h>
#include <math.h>

#define MAXN 100000
#define MAXE 1000000
#define HF   64
#define NPW  16          // nodes per warp in agg_pool
#define SBLK 1024        // scan block size

// ---------------- scratch (device globals) ------------------------------------
__device__ __align__(16) float4 g_acc[MAXN];      // {degw(incl self), cnt, den, num}
__device__ __align__(16) float  g_dis[MAXN];
__device__ __align__(16) float  g_nw[MAXN];
__device__ __align__(16) int    g_cnt2[MAXN];     // running scatter cursor (starts at offs)
__device__ __align__(16) int    g_bscan[MAXN];    // exclusive-in-block scan of cnt
__device__ __align__(16) int    g_bsum[128];
__device__ __align__(16) int    g_offs[MAXN + 1];
__device__ __align__(16) float2 g_edge[MAXE];     // .x = src (int bits), .y = norm
__device__ __align__(16) __half g_tA[(size_t)MAXN * HF];
__device__ __align__(16) __half g_tB[(size_t)MAXN * HF];
__device__ __align__(16) float  g_s[256 * HF];
__device__ __align__(16) float  g_wsum[256];

// ---------------- init ----------------------------------------------------------
__global__ void k_init(int n, int bn) {
    int i = blockIdx.x * blockDim.x + threadIdx.x;
    if (i < n) g_acc[i] = make_float4(1.0f, 0.0f, 0.0f, 0.0f);  // self-loop weight
    if (i < bn * HF) g_s[i] = 0.0f;
    if (i < bn)      g_wsum[i] = 0.0f;
}

// ---------------- single edge pass: 2 vector atomics per edge -------------------
// softmax shift-invariance: constant shift (w-1)/t, w in [0,1) -> no overflow.
__global__ void k_edge_setup(const int* __restrict__ row, const int* __restrict__ col,
                             const float* __restrict__ ew, int e) {
    int i = blockIdx.x * blockDim.x + threadIdx.x;
    if (i >= e) return;
    int r = row[i], c = col[i];
    float w = ew[i];
    float a = __expf((w - 1.0f) * 20.0f);
    float wa = w * a;
    atomicAdd(&g_acc[c], make_float4(w, 1.0f, a, wa));          // 16B RED
    atomicAdd(((float2*)&g_acc[r]) + 1, make_float2(a, wa));    // 8B RED on .zw
}

// ---- scan phase 1: per-block exclusive scan of cnt; fused node finish ----------
__global__ void k_scan1(int n) {
    __shared__ int sh[SBLK];
    int i = blockIdx.x * SBLK + threadIdx.x;
    int v = 0;
    if (i < n) {
        float4 ac = g_acc[i];
        v = (int)ac.y;
        g_dis[i] = rsqrtf(ac.x);                    // deg >= 1 (self-loop)
        g_nw[i] = (ac.z > 0.0f) ? ac.w / fmaxf(ac.z, 1e-16f) : 0.0f;
    }
    sh[threadIdx.x] = v;
    __syncthreads();
    for (int off = 1; off < SBLK; off <<= 1) {
        int t = (threadIdx.x >= off) ? sh[threadIdx.x - off] : 0;
        __syncthreads();
        sh[threadIdx.x] += t;
        __syncthreads();
    }
    if (i < n) g_bscan[i] = sh[threadIdx.x] - v;    // exclusive within block
    if (threadIdx.x == SBLK - 1) g_bsum[blockIdx.x] = sh[threadIdx.x];
}

// ---- scan phase 2+3 merged: each block reduces its segment prefix itself -------
// Block covers 256 consecutive nodes; 256 | 1024 so all share one segment.
__global__ void k_scan3(int n, int e, int nb) {
    __shared__ int red[256];
    int i = blockIdx.x * blockDim.x + threadIdx.x;
    int seg = (blockIdx.x * blockDim.x) / SBLK;     // same for whole block
    int t = threadIdx.x;
    red[t] = (t < seg && t < nb) ? g_bsum[t] : 0;   // sum of bsum[0..seg-1]
    __syncthreads();
    for (int off = 128; off > 0; off >>= 1) {
        if (t < off) red[t] += red[t + off];
        __syncthreads();
    }
    int prefix = red[0];
    if (i < n) {
        int o = prefix + g_bscan[i];
        g_offs[i] = o;
        g_cnt2[i] = o;                              // scatter cursor starts at offs
    }
    if (i == 0) g_offs[n] = e;
}

// scatter edges into destination-sorted order; pack (src, norm) into 8B
__global__ void k_edge_scatter(const int* __restrict__ row, const int* __restrict__ col,
                               const float* __restrict__ ew, int e) {
    int i = blockIdx.x * blockDim.x + threadIdx.x;
    if (i >= e) return;
    int r = row[i], c = col[i];
    int p = atomicAdd(&g_cnt2[c], 1);
    float2 pk;
    pk.x = __int_as_float(r);
    pk.y = g_dis[r] * ew[i] * g_dis[c];
    g_edge[p] = pk;
}

// ---------------- GEMM layer 1: x(fp32)[n,64] @ W1 -> fp16 ----------------------
__global__ void k_gemm64(const float* __restrict__ A, const float* __restrict__ W,
                         __half* __restrict__ C, int n) {
    __shared__ float As[64][65];
    __shared__ float Ws[64][64];
    int brow = blockIdx.x * 64;
    for (int i = threadIdx.x; i < 4096; i += 256) {
        int rr = i >> 6, cc = i & 63;
        Ws[rr][cc] = W[i];
        int gr = brow + rr;
        As[rr][cc] = (gr < n) ? A[(size_t)gr * HF + cc] : 0.0f;
    }
    __syncthreads();
    int r0 = (threadIdx.x >> 4) * 4;
    int c0 = (threadIdx.x & 15) * 4;
    float acc[4][4] = {};
#pragma unroll
    for (int k = 0; k < 64; k++) {
        float a0 = As[r0 + 0][k], a1 = As[r0 + 1][k], a2 = As[r0 + 2][k], a3 = As[r0 + 3][k];
        float4 w4 = *(const float4*)&Ws[k][c0];
        acc[0][0] += a0 * w4.x; acc[0][1] += a0 * w4.y; acc[0][2] += a0 * w4.z; acc[0][3] += a0 * w4.w;
        acc[1][0] += a1 * w4.x; acc[1][1] += a1 * w4.y; acc[1][2] += a1 * w4.z; acc[1][3] += a1 * w4.w;
        acc[2][0] += a2 * w4.x; acc[2][1] += a2 * w4.y; acc[2][2] += a2 * w4.z; acc[2][3] += a2 * w4.w;
        acc[3][0] += a3 * w4.x; acc[3][1] += a3 * w4.y; acc[3][2] += a3 * w4.z; acc[3][3] += a3 * w4.w;
    }
#pragma unroll
    for (int i = 0; i < 4; i++) {
        int gr = brow + r0 + i;
        if (gr < n) {
            __half2* dst = (__half2*)&C[(size_t)gr * HF + c0];
            dst[0] = __floats2half2_rn(acc[i][0], acc[i][1]);
            dst[1] = __floats2half2_rn(acc[i][2], acc[i][3]);
        }
    }
}

// ---------------- fused aggregate(+bias+LeakyReLU) -> GEMM ----------------------
__global__ void k_agg_gemm(const __half2* __restrict__ tmp, const float* __restrict__ bias,
                           const float* __restrict__ W, __half* __restrict__ C, int n) {
    __shared__ float As[64][65];
    __shared__ float Ws[64][64];
    int brow = blockIdx.x * 64;
    int wid = threadIdx.x >> 5;
    int lane = threadIdx.x & 31;

    for (int i = threadIdx.x; i < 4096; i += 256) {
        Ws[i >> 6][i & 63] = W[i];
    }

    float2 bb = ((const float2*)bias)[lane];
#pragma unroll
    for (int j = 0; j < 8; j++) {
        int rr = wid * 8 + j;
        int node = brow + rr;
        float ax = 0.0f, ay = 0.0f;
        if (node < n) {
            float d = g_dis[node];
            float sc = d * d;
            float2 self = __half22float2(tmp[(size_t)node * 32 + lane]);
            ax = sc * self.x;
            ay = sc * self.y;
            int p = g_offs[node], end = g_offs[node + 1];
            for (; p < end; ++p) {
                float2 pk = g_edge[p];
                int s = __float_as_int(pk.x);
                float2 v = __half22float2(tmp[(size_t)s * 32 + lane]);
                ax += pk.y * v.x;
                ay += pk.y * v.y;
            }
            ax += bb.x; ay += bb.y;
            ax = (ax > 0.0f) ? ax : 0.01f * ax;     // LeakyReLU
            ay = (ay > 0.0f) ? ay : 0.01f * ay;
        }
        As[rr][2 * lane]     = ax;
        As[rr][2 * lane + 1] = ay;
    }
    __syncthreads();

    int r0 = (threadIdx.x >> 4) * 4;
    int c0 = (threadIdx.x & 15) * 4;
    float acc[4][4] = {};
#pragma unroll
    for (int k = 0; k < 64; k++) {
        float a0 = As[r0 + 0][k], a1 = As[r0 + 1][k], a2 = As[r0 + 2][k], a3 = As[r0 + 3][k];
        float4 w4 = *(const float4*)&Ws[k][c0];
        acc[0][0] += a0 * w4.x; acc[0][1] += a0 * w4.y; acc[0][2] += a0 * w4.z; acc[0][3] += a0 * w4.w;
        acc[1][0] += a1 * w4.x; acc[1][1] += a1 * w4.y; acc[1][2] += a1 * w4.z; acc[1][3] += a1 * w4.w;
        acc[2][0] += a2 * w4.x; acc[2][1] += a2 * w4.y; acc[2][2] += a2 * w4.z; acc[2][3] += a2 * w4.w;
        acc[3][0] += a3 * w4.x; acc[3][1] += a3 * w4.y; acc[3][2] += a3 * w4.z; acc[3][3] += a3 * w4.w;
    }
#pragma unroll
    for (int i = 0; i < 4; i++) {
        int gr = brow + r0 + i;
        if (gr < n) {
            __half2* dst = (__half2*)&C[(size_t)gr * HF + c0];
            dst[0] = __floats2half2_rn(acc[i][0], acc[i][1]);
            dst[1] = __floats2half2_rn(acc[i][2], acc[i][3]);
        }
    }
}

// ---------------- fused layer-3 aggregation + weighted pooling ------------------
__global__ void k_agg_pool(const __half2* __restrict__ tmp, const float* __restrict__ bias,
                           const int* __restrict__ batch, int n) {
    int warp = (blockIdx.x * blockDim.x + threadIdx.x) >> 5;
    int lane = threadIdx.x & 31;
    int n0 = warp * NPW;
    if (n0 >= n) return;
    int n1 = min(n0 + NPW, n);
    float2 bb = ((const float2*)bias)[lane];
    float px = 0.0f, py = 0.0f, wacc = 0.0f;
    int cb = batch[n0];
    for (int node = n0; node < n1; node++) {
        int b = batch[node];
        if (b != cb) {
            atomicAdd(&g_s[cb * HF + 2 * lane],     px);
            atomicAdd(&g_s[cb * HF + 2 * lane + 1], py);
            if (lane == 0) atomicAdd(&g_wsum[cb], wacc);
            px = py = wacc = 0.0f;
            cb = b;
        }
        float d = g_dis[node];
        float sc = d * d;
        float2 self = __half22float2(tmp[(size_t)node * 32 + lane]);
        float ax = sc * self.x;
        float ay = sc * self.y;
        int p = g_offs[node], end = g_offs[node + 1];
        for (; p < end; ++p) {
            float2 pk = g_edge[p];
            int s = __float_as_int(pk.x);
            float2 v = __half22float2(tmp[(size_t)s * 32 + lane]);
            ax += pk.y * v.x;
            ay += pk.y * v.y;
        }
        float nwv = g_nw[node];
        px += nwv * (ax + bb.x);
        py += nwv * (ay + bb.y);
        wacc += nwv;
    }
    atomicAdd(&g_s[cb * HF + 2 * lane],     px);
    atomicAdd(&g_s[cb * HF + 2 * lane + 1], py);
    if (lane == 0) atomicAdd(&g_wsum[cb], wacc);
}

// ---------------- MLP head: one thread per graph ---------------------------------
__global__ void k_head(const float* __restrict__ Wlin, const float* __restrict__ blin,
                       const float* __restrict__ Wout, const float* __restrict__ bout,
                       float* __restrict__ out, int bn) {
    int b = blockIdx.x * blockDim.x + threadIdx.x;
    if (b >= bn) return;
    const int O_PROBS = bn * 10;
    const int O_FEATS = bn * 20;
    const int O_EMB   = O_FEATS + bn * 128;
    const int O_HOUT  = O_EMB + bn * 64;

    float feats[128];
    float ws = fmaxf(g_wsum[b], 1e-16f);
#pragma unroll
    for (int k = 0; k < HF; k++) {
        float sv = g_s[b * HF + k];
        feats[k] = sv;
        feats[HF + k] = sv / ws;
    }
    float emb[64], ho[64];
    for (int j = 0; j < 64; j++) {
        float a = blin[j];
        for (int i = 0; i < 128; i++) a += feats[i] * __ldg(&Wlin[i * 64 + j]);
        emb[j] = a;
        ho[j] = fmaxf(a, 0.0f);
    }
    float lg[10];
    for (int c = 0; c < 10; c++) {
        float a = bout[c];
        for (int j = 0; j < 64; j++) a += ho[j] * __ldg(&Wout[j * 10 + c]);
        lg[c] = a;
    }
    float mx = lg[0];
#pragma unroll
    for (int c = 1; c < 10; c++) mx = fmaxf(mx, lg[c]);
    float ex[10], den = 0.0f;
#pragma unroll
    for (int c = 0; c < 10; c++) { ex[c] = expf(lg[c] - mx); den += ex[c]; }
    float inv = 1.0f / den;

    for (int c = 0; c < 10; c++) {
        out[b * 10 + c] = lg[c];
        out[O_PROBS + b * 10 + c] = ex[c] * inv;
    }
    for (int i = 0; i < 128; i++) out[O_FEATS + b * 128 + i] = feats[i];
    for (int j = 0; j < 64; j++) {
        out[O_EMB  + b * 64 + j] = emb[j];
        out[O_HOUT + b * 64 + j] = ho[j];
    }
}

// ---------------------------------------------------------------------------------
extern "C" void kernel_launch(void* const* d_in, const int* in_sizes, int n_in,
                              void* d_out, int out_size) {
    const float* x    = (const float*)d_in[0];
    const int*   ei   = (const int*)  d_in[1];
    const float* ew   = (const float*)d_in[2];
    const int*   batch= (const int*)  d_in[3];
    const float* W1 = (const float*)d_in[4];  const float* b1 = (const float*)d_in[5];
    const float* W2 = (const float*)d_in[6];  const float* b2 = (const float*)d_in[7];
    const float* W3 = (const float*)d_in[8];  const float* b3 = (const float*)d_in[9];
    const float* Wlin = (const float*)d_in[10]; const float* blin = (const float*)d_in[11];
    const float* Wout = (const float*)d_in[12]; const float* bout = (const float*)d_in[13];
    float* out = (float*)d_out;

    int n  = in_sizes[0] / HF;
    int e  = in_sizes[2];
    int bn = out_size / 276;

    const int* row = ei;
    const int* col = ei + e;

    __half *p_tA, *p_tB;
    cudaGetSymbolAddress((void**)&p_tA, g_tA);
    cudaGetSymbolAddress((void**)&p_tB, g_tB);

    const int T = 256;
    int initMax = max(n, bn * HF);
    int nBlkE = (e + T - 1) / T;
    int nBlkP = ((((n + NPW - 1) / NPW) * 32) + T - 1) / T;
    int nb = (n + SBLK - 1) / SBLK;

    // setup
    k_init<<<(initMax + T - 1) / T, T>>>(n, bn);
    k_edge_setup<<<nBlkE, T>>>(row, col, ew, e);
    k_scan1<<<nb, SBLK>>>(n);
    k_scan3<<<(n + T - 1) / T, T>>>(n, e, nb);
    k_edge_scatter<<<nBlkE, T>>>(row, col, ew, e);

    int gemmBlks = (n + 63) / 64;
    // layer 1 GEMM
    k_gemm64<<<gemmBlks, 256>>>(x, W1, p_tA, n);
    // layer 1 aggregate + LeakyReLU fused with layer 2 GEMM
    k_agg_gemm<<<gemmBlks, 256>>>((const __half2*)p_tA, b1, W2, p_tB, n);
    // layer 2 aggregate + LeakyReLU fused with layer 3 GEMM
    k_agg_gemm<<<gemmBlks, 256>>>((const __half2*)p_tB, b2, W3, p_tA, n);
    // layer 3 aggregate fused with pooling
    k_agg_pool<<<nBlkP, T>>>((const __half2*)p_tA, b3, batch, n);

    // head
    k_head<<<(bn + 127) / 128, 128>>>(Wlin, blin, Wout, bout, out, bn);
}